// round 10
// baseline (speedup 1.0000x reference)
#include <cuda_runtime.h>
#include <math.h>
#include <stdint.h>

#define B_   2
#define T_   2048
#define D_   1024
#define H_   16
#define HKV_ 4
#define HD_  64
#define G_   4

#define QKVD 1536      // fused qkv row width: 1024 q | 256 k | 256 v
#define KOFF 1024
#define VOFF 1280

// Scratch (static device globals — no allocation in kernel_launch)
__device__ float g_qkv[(size_t)B_ * T_ * QKVD];
__device__ float g_vt[(size_t)B_ * HKV_ * HD_ * T_];   // V transposed: [b][kvh][d][t]
__device__ float g_o[(size_t)B_ * T_ * D_];
// pre-rounded (tf32) copies: x | Wq | Wk | Wv | Wp
#define PRE_X  0
#define PRE_WQ (4096 * 1024)
#define PRE_WK (PRE_WQ + 1024 * 1024)
#define PRE_WV (PRE_WK + 256 * 1024)
#define PRE_WP (PRE_WV + 256 * 1024)
#define PRE_TOTAL (PRE_WP + 1024 * 1024)
__device__ float g_pre[(size_t)PRE_TOTAL];

__device__ __forceinline__ float to_tf32(float x) {
    float r;
    asm("cvt.rna.tf32.f32 %0, %1;" : "=f"(r) : "f"(x));
    return r;
}

__device__ __forceinline__ void mma_tf32(float* d, const uint32_t* a, const uint32_t* b) {
    asm volatile(
        "mma.sync.aligned.m16n8k8.row.col.f32.tf32.tf32.f32 "
        "{%0,%1,%2,%3}, {%4,%5,%6,%7}, {%8,%9}, {%0,%1,%2,%3};"
        : "+f"(d[0]), "+f"(d[1]), "+f"(d[2]), "+f"(d[3])
        : "r"(a[0]), "r"(a[1]), "r"(a[2]), "r"(a[3]), "r"(b[0]), "r"(b[1]));
}

__device__ __forceinline__ uint32_t smem_u32(const void* p) {
    return (uint32_t)__cvta_generic_to_shared(p);
}

__device__ __forceinline__ void ldm_x4(uint32_t* r, uint32_t a) {
    asm volatile("ldmatrix.sync.aligned.m8n8.x4.shared.b16 {%0,%1,%2,%3}, [%4];"
        : "=r"(r[0]), "=r"(r[1]), "=r"(r[2]), "=r"(r[3]) : "r"(a));
}

__device__ __forceinline__ void cp16(uint32_t dst, const void* src) {
    asm volatile("cp.async.cg.shared.global [%0], [%1], 16;" :: "r"(dst), "l"(src));
}
__device__ __forceinline__ void cp_commit() {
    asm volatile("cp.async.commit_group;");
}
__device__ __forceinline__ void cp_wait1() {
    asm volatile("cp.async.wait_group 1;");
}

// ---------------------------------------------------------------------------
// Pre-round inputs to tf32 (rna) into g_pre.
// ---------------------------------------------------------------------------
__global__ void preround_kernel(const float* __restrict__ x,
                                const float* __restrict__ Wq,
                                const float* __restrict__ Wk,
                                const float* __restrict__ Wv,
                                const float* __restrict__ Wp)
{
    int i4 = blockIdx.x * blockDim.x + threadIdx.x;
    int i = i4 * 4;
    if (i >= PRE_TOTAL) return;
    const float* src;
    int off;
    if (i < PRE_WQ)      { src = x;  off = i - PRE_X;  }
    else if (i < PRE_WK) { src = Wq; off = i - PRE_WQ; }
    else if (i < PRE_WV) { src = Wk; off = i - PRE_WK; }
    else if (i < PRE_WP) { src = Wv; off = i - PRE_WV; }
    else                 { src = Wp; off = i - PRE_WP; }
    float4 v = *(const float4*)(src + off);
    *(float4*)(g_pre + i) = make_float4(to_tf32(v.x), to_tf32(v.y), to_tf32(v.z), to_tf32(v.w));
}

// ---------------------------------------------------------------------------
// TF32 GEMM mainloop (128x128 tile, K-chunk 32, 8 warps 2m x 4n)
// 3-stage cp.async (prefetch distance 2), ONE barrier per chunk.
// Pitch 36 -> conflict-free ldmatrix (unit = 9*row + c/4, distinct mod 8).
// Dynamic SMEM: 2 * 3 * 128*36*4 = 110592 B -> 2 CTAs/SM.
// ---------------------------------------------------------------------------
#define GP 36
#define SBY (128 * GP * 4)
#define GEMM_SMEM (6 * SBY)

#define GEMM_MAIN(BSEL, NBASE)                                                             \
    extern __shared__ float gsm[];                                                        \
    float* As = gsm;                                                                       \
    float* Bs = gsm + 3 * 128 * GP;                                                        \
    const int m0   = blockIdx.y * 128;                                                     \
    const int t    = threadIdx.x;                                                          \
    const int lane = t & 31;                                                               \
    const int wid  = t >> 5;                                                               \
    const int wm   = (wid >> 2) * 64;                                                      \
    const int wn   = (wid & 3) * 32;                                                       \
    const int lr = t >> 1;                                                                 \
    const int kg = (t & 1) * 16;                                                           \
    const uint32_t As_u = smem_u32(As);                                                    \
    const uint32_t Bs_u = smem_u32(Bs);                                                    \
    const uint32_t a_st = As_u + 4u * (lr * GP + kg);                                      \
    const uint32_t b_st = Bs_u + 4u * (lr * GP + kg);                                      \
    const int a_off = ((lane & 7) + ((lane >> 3) & 1) * 8) * GP + ((lane >> 4) & 1) * 4;   \
    const int b_off = ((lane & 7) + ((lane >> 4) & 1) * 8) * GP + ((lane >> 3) & 1) * 4;   \
    float acc[4][4][4];                                                                    \
    _Pragma("unroll") for (int i = 0; i < 4; i++)                                          \
    _Pragma("unroll") for (int j = 0; j < 4; j++)                                          \
    _Pragma("unroll") for (int r = 0; r < 4; r++) acc[i][j][r] = 0.f;                      \
    const float* Abase = A + (size_t)(m0 + lr) * K + kg;                                   \
    const float* Bbase = (BSEL) + (size_t)((NBASE) + lr) * K + kg;                         \
    const int nk = K / 32;                                                                 \
    _Pragma("unroll") for (int s = 0; s < 2; s++) {                                        \
        _Pragma("unroll") for (int u = 0; u < 4; u++) {                                    \
            cp16(a_st + s * SBY + 16 * u, Abase + s * 32 + 4 * u);                         \
            cp16(b_st + s * SBY + 16 * u, Bbase + s * 32 + 4 * u);                         \
        }                                                                                  \
        cp_commit();                                                                       \
    }                                                                                      \
    for (int it = 0; it < nk; it++) {                                                      \
        cp_wait1();                                                                        \
        __syncthreads();                                                                   \
        if (it + 2 < nk) {                                                                 \
            const int buf = (it + 2) % 3;                                                  \
            _Pragma("unroll") for (int u = 0; u < 4; u++) {                                \
                cp16(a_st + buf * SBY + 16 * u, Abase + (it + 2) * 32 + 4 * u);            \
                cp16(b_st + buf * SBY + 16 * u, Bbase + (it + 2) * 32 + 4 * u);            \
            }                                                                              \
        }                                                                                  \
        cp_commit();                                                                       \
        const int cur = it % 3;                                                            \
        const uint32_t abuf = As_u + (uint32_t)cur * SBY;                                  \
        const uint32_t bbuf = Bs_u + (uint32_t)cur * SBY;                                  \
        _Pragma("unroll")                                                                  \
        for (int ks2 = 0; ks2 < 4; ks2++) {                                                \
            uint32_t af[4][4], bf[2][4];                                                   \
            _Pragma("unroll") for (int mf = 0; mf < 4; mf++)                               \
                ldm_x4(af[mf], abuf + 4u * ((wm + mf * 16) * GP + ks2 * 8 + a_off));       \
            _Pragma("unroll") for (int np = 0; np < 2; np++)                               \
                ldm_x4(bf[np], bbuf + 4u * ((wn + np * 16) * GP + ks2 * 8 + b_off));       \
            _Pragma("unroll") for (int mf = 0; mf < 4; mf++)                               \
            _Pragma("unroll") for (int np = 0; np < 2; np++) {                             \
                mma_tf32(acc[mf][np * 2],     af[mf], bf[np]);                             \
                mma_tf32(acc[mf][np * 2 + 1], af[mf], bf[np] + 2);                         \
            }                                                                              \
        }                                                                                  \
    }

__global__ __launch_bounds__(256, 2) void gemm_tf32_nt(
    const float* __restrict__ A, const float* __restrict__ B,
    float* __restrict__ C, int M, int N, int K)
{
    GEMM_MAIN(B, blockIdx.x * 128)
    const int n0 = blockIdx.x * 128;
#pragma unroll
    for (int mf = 0; mf < 4; mf++)
#pragma unroll
        for (int nf = 0; nf < 4; nf++) {
            const int row = m0 + wm + mf * 16 + (lane >> 2);
            const int col = n0 + wn + nf * 8 + (lane & 3) * 2;
            *(float2*)(C + (size_t)row * N + col)       = make_float2(acc[mf][nf][0], acc[mf][nf][1]);
            *(float2*)(C + (size_t)(row + 8) * N + col) = make_float2(acc[mf][nf][2], acc[mf][nf][3]);
        }
}

// QKV GEMM: q/k blocks -> g_qkv rows (tf32-rounded); v blocks -> g_vt TRANSPOSED.
__global__ __launch_bounds__(256, 2) void gemm_qkv(
    const float* __restrict__ A, const float* __restrict__ Wq,
    const float* __restrict__ Wk, const float* __restrict__ Wv,
    float* __restrict__ C, int M, int K)
{
    const int nblk = blockIdx.x * 128;
    const float* Bsel; int nbase;
    if (nblk < KOFF)      { Bsel = Wq; nbase = nblk; }
    else if (nblk < VOFF) { Bsel = Wk; nbase = nblk - KOFF; }
    else                  { Bsel = Wv; nbase = nblk - VOFF; }
    GEMM_MAIN(Bsel, nbase)
    if (nblk < VOFF) {
#pragma unroll
        for (int mf = 0; mf < 4; mf++)
#pragma unroll
            for (int nf = 0; nf < 4; nf++) {
                const int row = m0 + wm + mf * 16 + (lane >> 2);
                const int col = nblk + wn + nf * 8 + (lane & 3) * 2;
                *(float2*)(C + (size_t)row * QKVD + col) =
                    make_float2(to_tf32(acc[mf][nf][0]), to_tf32(acc[mf][nf][1]));
                *(float2*)(C + (size_t)(row + 8) * QKVD + col) =
                    make_float2(to_tf32(acc[mf][nf][2]), to_tf32(acc[mf][nf][3]));
            }
    } else {
        // V: write transposed g_vt[b][kvh][d][t]
#pragma unroll
        for (int mf = 0; mf < 4; mf++)
#pragma unroll
            for (int nf = 0; nf < 4; nf++) {
                const int row = m0 + wm + mf * 16 + (lane >> 2);   // token index
                const int col = (nbase) + wn + nf * 8 + (lane & 3) * 2;  // v feature 0..255
                const int kvh = col >> 6, d = col & 63;
                const int b = row >> 11, tok = row & 2047;
                float* base = g_vt + ((size_t)((b * HKV_ + kvh) * HD_ + d)) * T_ + tok;
                base[0]      = to_tf32(acc[mf][nf][0]);
                base[T_]     = to_tf32(acc[mf][nf][1]);
                base[8]      = to_tf32(acc[mf][nf][2]);
                base[T_ + 8] = to_tf32(acc[mf][nf][3]);
            }
    }
}

// ---------------------------------------------------------------------------
// RoPE in-place on g_qkv (q and k only); q scaled by q_gain[h]/sqrt(HD).
// ---------------------------------------------------------------------------
__global__ void rope_kernel(const float* __restrict__ q_gain)
{
    const int total_q = B_ * T_ * H_ * (HD_ / 2);
    const int total_k = B_ * T_ * HKV_ * (HD_ / 2);
    int idx = blockIdx.x * blockDim.x + threadIdx.x;
    if (idx >= total_q + total_k) return;

    const float LN = logf(10000.0f);
    if (idx < total_q) {
        int j = idx & 31;
        int h = (idx >> 5) & 15;
        int t = (idx >> 9) & 2047;
        int b = idx >> 20;
        float invf = expf(-LN * ((float)(2 * j) / (float)HD_));
        float f = (float)t * invf;
        float c = cosf(f), s = sinf(f);
        float* base = g_qkv + ((size_t)(b * T_ + t)) * QKVD + h * HD_;
        float x1 = base[j], x2 = base[j + 32];
        float gain = q_gain[h] * 0.125f;
        base[j]      = to_tf32((x1 * c - x2 * s) * gain);
        base[j + 32] = to_tf32((x1 * s + x2 * c) * gain);
    } else {
        int i2 = idx - total_q;
        int j  = i2 & 31;
        int kv = (i2 >> 5) & 3;
        int t  = (i2 >> 7) & 2047;
        int b  = i2 >> 18;
        float invf = expf(-LN * ((float)(2 * j) / (float)HD_));
        float f = (float)t * invf;
        float c = cosf(f), s = sinf(f);
        float* base = g_qkv + ((size_t)(b * T_ + t)) * QKVD + KOFF + kv * HD_;
        float x1 = base[j], x2 = base[j + 32];
        base[j]      = to_tf32(x1 * c - x2 * s);
        base[j + 32] = to_tf32(x1 * s + x2 * c);
    }
}

// ---------------------------------------------------------------------------
// Tensor-core flash attention (causal, GQA), cp.async double-buffered K/V^T.
// No-max softmax: p = exp(min(s,80)); normalize once at the end.
// ---------------------------------------------------------------------------
#define FP2 68
#define TILEB (64 * FP2 * 4)
#define FLASH_SMEM ((2 * 64 + 2 * 64 + 128) * FP2 * 4)   // 104448 B

__global__ __launch_bounds__(256, 2) void flash_tc()
{
    extern __shared__ float sm[];
    float* Ks = sm;                      // [2][64 s][FP2] (cols = d)
    float* Vt = sm + 2 * 64 * FP2;       // [2][64 d][FP2] (cols = s)
    float* Ps = sm + 4 * 64 * FP2;       // [128 q][FP2]   (cols = s)

    const int qt   = (int)gridDim.x - 1 - (int)blockIdx.x;  // heavy blocks first
    const int h    = blockIdx.y;
    const int b    = blockIdx.z;
    const int tid  = threadIdx.x;
    const int lane = tid & 31;
    const int wid  = tid >> 5;
    const int wm   = wid * 16;
    const int kvh  = h >> 2;
    const int r0   = lane >> 2;
    const int c0   = lane & 3;

    const uint32_t Ks_u = smem_u32(Ks);
    const uint32_t Vt_u = smem_u32(Vt);
    const uint32_t Ps_u = smem_u32(Ps);

    const int kf_off = (lane & 7) * FP2 + (lane >> 3) * 4;   // K/V B-frag
    const int pa_off = ((lane & 7) + ((lane >> 3) & 1) * 8) * FP2 + ((lane >> 4) & 1) * 4;

    const int ld_r = tid >> 2;
    const int ld_c = (tid & 3) * 16;
    const float* kgbase = g_qkv + ((size_t)(b * T_ + ld_r)) * QKVD + KOFF + kvh * HD_ + ld_c;
    const float* vgbase = g_vt + ((size_t)((b * HKV_ + kvh) * HD_ + ld_r)) * T_ + ld_c;
    const uint32_t ks_dst = Ks_u + 4u * (ld_r * FP2 + ld_c);
    const uint32_t vt_dst = Vt_u + 4u * (ld_r * FP2 + ld_c);

#define ISSUE_TILE(S0, BUF)                                                   \
    {                                                                         \
        const float* kg = kgbase + (size_t)(S0) * QKVD;                       \
        const float* vg = vgbase + (S0);                                      \
        _Pragma("unroll") for (int u = 0; u < 4; u++) {                       \
            cp16(ks_dst + (BUF) * TILEB + 16 * u, kg + 4 * u);                \
            cp16(vt_dst + (BUF) * TILEB + 16 * u, vg + 4 * u);                \
        }                                                                     \
    }

    // Q fragments in registers (already tf32)
    uint32_t qf[8][4];
    {
        const float* q0 = g_qkv + ((size_t)(b * T_ + qt * 128 + wm + r0)) * QKVD + h * HD_;
        const float* q1 = q0 + (size_t)8 * QKVD;
#pragma unroll
        for (int kb = 0; kb < 8; kb++) {
            qf[kb][0] = __float_as_uint(q0[kb * 8 + c0]);
            qf[kb][1] = __float_as_uint(q1[kb * 8 + c0]);
            qf[kb][2] = __float_as_uint(q0[kb * 8 + c0 + 4]);
            qf[kb][3] = __float_as_uint(q1[kb * 8 + c0 + 4]);
        }
    }

    float oacc[8][4];
#pragma unroll
    for (int nf = 0; nf < 8; nf++)
#pragma unroll
        for (int r = 0; r < 4; r++) oacc[nf][r] = 0.f;
    float lp0 = 0.f, lp1 = 0.f;

    const int qi0 = qt * 128 + wm + r0;
    const int qi1 = qi0 + 8;
    const int ntiles = (qt + 1) * 2;

    ISSUE_TILE(0, 0); cp_commit();
    ISSUE_TILE(64, 1); cp_commit();

    for (int it = 0; it < ntiles; it++) {
        const int s0 = it * 64;
        cp_wait1();
        __syncthreads();
        const uint32_t ksb = Ks_u + (uint32_t)(it & 1) * TILEB;
        const uint32_t vtb = Vt_u + (uint32_t)(it & 1) * TILEB;

        if (s0 <= qt * 128 + wm + 15) {
            float sacc[8][4];
#pragma unroll
            for (int nf = 0; nf < 8; nf++)
#pragma unroll
                for (int r = 0; r < 4; r++) sacc[nf][r] = 0.f;

#pragma unroll
            for (int kbp = 0; kbp < 4; kbp++) {
#pragma unroll
                for (int nf = 0; nf < 8; nf++) {
                    uint32_t kb4[4];
                    ldm_x4(kb4, ksb + 4u * (nf * 8 * FP2 + kbp * 16 + kf_off));
                    mma_tf32(sacc[nf], qf[2 * kbp],     kb4);
                    mma_tf32(sacc[nf], qf[2 * kbp + 1], kb4 + 2);
                }
            }

            if (s0 + 63 > qt * 128 + wm) {
#pragma unroll
                for (int nf = 0; nf < 8; nf++) {
                    int sj = s0 + nf * 8 + 2 * c0;
                    if (sj > qi0)     sacc[nf][0] = -1e30f;
                    if (sj + 1 > qi0) sacc[nf][1] = -1e30f;
                    if (sj > qi1)     sacc[nf][2] = -1e30f;
                    if (sj + 1 > qi1) sacc[nf][3] = -1e30f;
                }
            }

#pragma unroll
            for (int nf = 0; nf < 8; nf++) {
                float p0 = to_tf32(__expf(fminf(sacc[nf][0], 80.f)));
                float p1 = to_tf32(__expf(fminf(sacc[nf][1], 80.f)));
                float p2 = to_tf32(__expf(fminf(sacc[nf][2], 80.f)));
                float p3 = to_tf32(__expf(fminf(sacc[nf][3], 80.f)));
                lp0 += p0 + p1; lp1 += p2 + p3;
                *(float2*)&Ps[(wm + r0)     * FP2 + nf * 8 + 2 * c0] = make_float2(p0, p1);
                *(float2*)&Ps[(wm + r0 + 8) * FP2 + nf * 8 + 2 * c0] = make_float2(p2, p3);
            }

            __syncwarp();

#pragma unroll
            for (int kbp = 0; kbp < 4; kbp++) {
                uint32_t pa0[4], pa1[4];
                ldm_x4(pa0, Ps_u + 4u * (wm * FP2 + (2 * kbp)     * 8 + pa_off));
                ldm_x4(pa1, Ps_u + 4u * (wm * FP2 + (2 * kbp + 1) * 8 + pa_off));
#pragma unroll
                for (int nf = 0; nf < 8; nf++) {
                    uint32_t vb[4];
                    ldm_x4(vb, vtb + 4u * (nf * 8 * FP2 + kbp * 16 + kf_off));
                    mma_tf32(oacc[nf], pa0, vb);
                    mma_tf32(oacc[nf], pa1, vb + 2);
                }
            }
        }
        __syncthreads();
        if (it + 2 < ntiles) ISSUE_TILE(s0 + 128, it & 1);
        cp_commit();
    }

    lp0 += __shfl_xor_sync(0xffffffff, lp0, 1);
    lp0 += __shfl_xor_sync(0xffffffff, lp0, 2);
    lp1 += __shfl_xor_sync(0xffffffff, lp1, 1);
    lp1 += __shfl_xor_sync(0xffffffff, lp1, 2);
    float il0 = 1.0f / lp0, il1 = 1.0f / lp1;
    float* o0 = g_o + ((size_t)(b * T_ + qi0)) * D_ + h * HD_;
    float* o1 = g_o + ((size_t)(b * T_ + qi1)) * D_ + h * HD_;
#pragma unroll
    for (int nf = 0; nf < 8; nf++) {
        *(float2*)(o0 + nf * 8 + 2 * c0) = make_float2(to_tf32(oacc[nf][0] * il0), to_tf32(oacc[nf][1] * il0));
        *(float2*)(o1 + nf * 8 + 2 * c0) = make_float2(to_tf32(oacc[nf][2] * il1), to_tf32(oacc[nf][3] * il1));
    }
}

// ---------------------------------------------------------------------------
// Launch
// ---------------------------------------------------------------------------
extern "C" void kernel_launch(void* const* d_in, const int* in_sizes, int n_in,
                              void* d_out, int out_size)
{
    (void)in_sizes; (void)n_in; (void)out_size;
    const float* x      = (const float*)d_in[0];
    const float* Wq     = (const float*)d_in[1];
    const float* Wk     = (const float*)d_in[2];
    const float* Wv     = (const float*)d_in[3];
    const float* Wp     = (const float*)d_in[4];
    const float* q_gain = (const float*)d_in[5];
    float* out = (float*)d_out;

    float *qkvb, *ob, *pre;
    cudaGetSymbolAddress((void**)&qkvb, g_qkv);
    cudaGetSymbolAddress((void**)&ob, g_o);
    cudaGetSymbolAddress((void**)&pre, g_pre);

    cudaFuncSetAttribute(flash_tc, cudaFuncAttributeMaxDynamicSharedMemorySize, FLASH_SMEM);
    cudaFuncSetAttribute(gemm_qkv, cudaFuncAttributeMaxDynamicSharedMemorySize, GEMM_SMEM);
    cudaFuncSetAttribute(gemm_tf32_nt, cudaFuncAttributeMaxDynamicSharedMemorySize, GEMM_SMEM);

    const int M = B_ * T_;   // 4096

    preround_kernel<<<(PRE_TOTAL / 4 + 255) / 256, 256>>>(x, Wq, Wk, Wv, Wp);

    gemm_qkv<<<dim3(QKVD / 128, M / 128), 256, GEMM_SMEM>>>(
        pre + PRE_X, pre + PRE_WQ, pre + PRE_WK, pre + PRE_WV, qkvb, M, D_);

    const int total = B_ * T_ * (H_ + HKV_) * (HD_ / 2);
    rope_kernel<<<(total + 255) / 256, 256>>>(q_gain);

    flash_tc<<<dim3(T_ / 128, H_, B_), 256, FLASH_SMEM>>>();

    gemm_tf32_nt<<<dim3(D_ / 128, M / 128), 256, GEMM_SMEM>>>(ob, pre + PRE_WP, out, M, D_, D_);
}

// round 11
// speedup vs baseline: 1.0793x; 1.0793x over previous
#include <cuda_runtime.h>
#include <math.h>
#include <stdint.h>

#define B_   2
#define T_   2048
#define D_   1024
#define H_   16
#define HKV_ 4
#define HD_  64
#define G_   4

#define QKVD 1536      // fused qkv row width: 1024 q | 256 k | 256 v
#define KOFF 1024
#define VOFF 1280

// Scratch (static device globals — no allocation in kernel_launch)
__device__ float g_qkv[(size_t)B_ * T_ * QKVD];
__device__ float g_vt[(size_t)B_ * HKV_ * HD_ * T_];   // V transposed: [b][kvh][d][t]
__device__ float g_o[(size_t)B_ * T_ * D_];
// pre-rounded (tf32) copies: x | Wq | Wk | Wv | Wp
#define PRE_X  0
#define PRE_WQ (4096 * 1024)
#define PRE_WK (PRE_WQ + 1024 * 1024)
#define PRE_WV (PRE_WK + 256 * 1024)
#define PRE_WP (PRE_WV + 256 * 1024)
#define PRE_TOTAL (PRE_WP + 1024 * 1024)
__device__ float g_pre[(size_t)PRE_TOTAL];

__device__ __forceinline__ float to_tf32(float x) {
    float r;
    asm("cvt.rna.tf32.f32 %0, %1;" : "=f"(r) : "f"(x));
    return r;
}

__device__ __forceinline__ float ex2f(float x) {
    float r;
    asm("ex2.approx.f32 %0, %1;" : "=f"(r) : "f"(x));
    return r;
}

__device__ __forceinline__ void mma_tf32(float* d, const uint32_t* a, const uint32_t* b) {
    asm volatile(
        "mma.sync.aligned.m16n8k8.row.col.f32.tf32.tf32.f32 "
        "{%0,%1,%2,%3}, {%4,%5,%6,%7}, {%8,%9}, {%0,%1,%2,%3};"
        : "+f"(d[0]), "+f"(d[1]), "+f"(d[2]), "+f"(d[3])
        : "r"(a[0]), "r"(a[1]), "r"(a[2]), "r"(a[3]), "r"(b[0]), "r"(b[1]));
}

__device__ __forceinline__ uint32_t smem_u32(const void* p) {
    return (uint32_t)__cvta_generic_to_shared(p);
}

__device__ __forceinline__ void ldm_x4(uint32_t* r, uint32_t a) {
    asm volatile("ldmatrix.sync.aligned.m8n8.x4.shared.b16 {%0,%1,%2,%3}, [%4];"
        : "=r"(r[0]), "=r"(r[1]), "=r"(r[2]), "=r"(r[3]) : "r"(a));
}

__device__ __forceinline__ void cp16(uint32_t dst, const void* src) {
    asm volatile("cp.async.cg.shared.global [%0], [%1], 16;" :: "r"(dst), "l"(src));
}
__device__ __forceinline__ void cp_commit() {
    asm volatile("cp.async.commit_group;");
}
__device__ __forceinline__ void cp_wait1() {
    asm volatile("cp.async.wait_group 1;");
}

// ---------------------------------------------------------------------------
// Pre-round inputs to tf32 (rna) into g_pre.
// ---------------------------------------------------------------------------
__global__ void preround_kernel(const float* __restrict__ x,
                                const float* __restrict__ Wq,
                                const float* __restrict__ Wk,
                                const float* __restrict__ Wv,
                                const float* __restrict__ Wp)
{
    int i4 = blockIdx.x * blockDim.x + threadIdx.x;
    int i = i4 * 4;
    if (i >= PRE_TOTAL) return;
    const float* src;
    int off;
    if (i < PRE_WQ)      { src = x;  off = i - PRE_X;  }
    else if (i < PRE_WK) { src = Wq; off = i - PRE_WQ; }
    else if (i < PRE_WV) { src = Wk; off = i - PRE_WK; }
    else if (i < PRE_WP) { src = Wv; off = i - PRE_WV; }
    else                 { src = Wp; off = i - PRE_WP; }
    float4 v = *(const float4*)(src + off);
    *(float4*)(g_pre + i) = make_float4(to_tf32(v.x), to_tf32(v.y), to_tf32(v.z), to_tf32(v.w));
}

// ---------------------------------------------------------------------------
// TF32 GEMM mainloop (128x128 tile, K-chunk 16, 8 warps 2m x 4n)
// 3-stage cp.async, single barrier per chunk, no inner-loop cvt.  (R8 config)
// ---------------------------------------------------------------------------
#define GP 20
#define SBYTES (128 * GP * 4)

#define GEMM_MAIN(BSEL, NBASE)                                                             \
    __shared__ float As[3][128][GP];                                                       \
    __shared__ float Bs[3][128][GP];                                                       \
    const int m0   = blockIdx.y * 128;                                                     \
    const int t    = threadIdx.x;                                                          \
    const int lane = t & 31;                                                               \
    const int wid  = t >> 5;                                                               \
    const int wm   = (wid >> 2) * 64;                                                      \
    const int wn   = (wid & 3) * 32;                                                       \
    const int lr = t >> 1;                                                                 \
    const int kg = (t & 1) * 8;                                                            \
    const uint32_t As_u = smem_u32(&As[0][0][0]);                                          \
    const uint32_t Bs_u = smem_u32(&Bs[0][0][0]);                                          \
    const uint32_t a_st = As_u + 4u * (lr * GP + kg);                                      \
    const uint32_t b_st = Bs_u + 4u * (lr * GP + kg);                                      \
    const int a_off = ((lane & 7) + ((lane >> 3) & 1) * 8) * GP + ((lane >> 4) & 1) * 4;   \
    const int b_off = ((lane & 7) + ((lane >> 4) & 1) * 8) * GP + ((lane >> 3) & 1) * 4;   \
    float acc[4][4][4];                                                                    \
    _Pragma("unroll") for (int i = 0; i < 4; i++)                                          \
    _Pragma("unroll") for (int j = 0; j < 4; j++)                                          \
    _Pragma("unroll") for (int r = 0; r < 4; r++) acc[i][j][r] = 0.f;                      \
    const float* Abase = A + (size_t)(m0 + lr) * K + kg;                                   \
    const float* Bbase = (BSEL) + (size_t)((NBASE) + lr) * K + kg;                         \
    const int nk = K / 16;                                                                 \
    _Pragma("unroll") for (int s = 0; s < 2; s++) {                                        \
        cp16(a_st + s * SBYTES,      Abase + s * 16);                                      \
        cp16(a_st + s * SBYTES + 16, Abase + s * 16 + 4);                                  \
        cp16(b_st + s * SBYTES,      Bbase + s * 16);                                      \
        cp16(b_st + s * SBYTES + 16, Bbase + s * 16 + 4);                                  \
        cp_commit();                                                                       \
    }                                                                                      \
    for (int it = 0; it < nk; it++) {                                                      \
        cp_wait1();                                                                        \
        __syncthreads();                                                                   \
        if (it + 2 < nk) {                                                                 \
            const int buf = (it + 2) % 3;                                                  \
            cp16(a_st + buf * SBYTES,      Abase + (it + 2) * 16);                         \
            cp16(a_st + buf * SBYTES + 16, Abase + (it + 2) * 16 + 4);                     \
            cp16(b_st + buf * SBYTES,      Bbase + (it + 2) * 16);                         \
            cp16(b_st + buf * SBYTES + 16, Bbase + (it + 2) * 16 + 4);                     \
        }                                                                                  \
        cp_commit();                                                                       \
        const int cur = it % 3;                                                            \
        const uint32_t abuf = As_u + (uint32_t)cur * SBYTES;                               \
        const uint32_t bbuf = Bs_u + (uint32_t)cur * SBYTES;                               \
        uint32_t af[2][4][4], bf[2][2][4];                                                 \
        _Pragma("unroll") for (int ks2 = 0; ks2 < 2; ks2++) {                              \
            _Pragma("unroll") for (int mf = 0; mf < 4; mf++)                               \
                ldm_x4(af[ks2][mf], abuf + 4u * ((wm + mf * 16) * GP + ks2 * 8 + a_off));  \
            _Pragma("unroll") for (int np = 0; np < 2; np++)                               \
                ldm_x4(bf[ks2][np], bbuf + 4u * ((wn + np * 16) * GP + ks2 * 8 + b_off));  \
        }                                                                                  \
        _Pragma("unroll") for (int ks2 = 0; ks2 < 2; ks2++)                                \
        _Pragma("unroll") for (int mf = 0; mf < 4; mf++)                                   \
        _Pragma("unroll") for (int np = 0; np < 2; np++) {                                 \
            mma_tf32(acc[mf][np * 2],     af[ks2][mf], bf[ks2][np]);                       \
            mma_tf32(acc[mf][np * 2 + 1], af[ks2][mf], bf[ks2][np] + 2);                   \
        }                                                                                  \
    }

__global__ __launch_bounds__(256, 2) void gemm_tf32_nt(
    const float* __restrict__ A, const float* __restrict__ B,
    float* __restrict__ C, int M, int N, int K)
{
    GEMM_MAIN(B, blockIdx.x * 128)
    const int n0 = blockIdx.x * 128;
#pragma unroll
    for (int mf = 0; mf < 4; mf++)
#pragma unroll
        for (int nf = 0; nf < 4; nf++) {
            const int row = m0 + wm + mf * 16 + (lane >> 2);
            const int col = n0 + wn + nf * 8 + (lane & 3) * 2;
            *(float2*)(C + (size_t)row * N + col)       = make_float2(acc[mf][nf][0], acc[mf][nf][1]);
            *(float2*)(C + (size_t)(row + 8) * N + col) = make_float2(acc[mf][nf][2], acc[mf][nf][3]);
        }
}

// QKV GEMM: q/k blocks -> g_qkv rows (tf32-rounded); v blocks -> g_vt TRANSPOSED.
__global__ __launch_bounds__(256, 2) void gemm_qkv(
    const float* __restrict__ A, const float* __restrict__ Wq,
    const float* __restrict__ Wk, const float* __restrict__ Wv,
    float* __restrict__ C, int M, int K)
{
    const int nblk = blockIdx.x * 128;
    const float* Bsel; int nbase;
    if (nblk < KOFF)      { Bsel = Wq; nbase = nblk; }
    else if (nblk < VOFF) { Bsel = Wk; nbase = nblk - KOFF; }
    else                  { Bsel = Wv; nbase = nblk - VOFF; }
    GEMM_MAIN(Bsel, nbase)
    if (nblk < VOFF) {
#pragma unroll
        for (int mf = 0; mf < 4; mf++)
#pragma unroll
            for (int nf = 0; nf < 4; nf++) {
                const int row = m0 + wm + mf * 16 + (lane >> 2);
                const int col = nblk + wn + nf * 8 + (lane & 3) * 2;
                *(float2*)(C + (size_t)row * QKVD + col) =
                    make_float2(to_tf32(acc[mf][nf][0]), to_tf32(acc[mf][nf][1]));
                *(float2*)(C + (size_t)(row + 8) * QKVD + col) =
                    make_float2(to_tf32(acc[mf][nf][2]), to_tf32(acc[mf][nf][3]));
            }
    } else {
        // V: write transposed g_vt[b][kvh][d][t]
#pragma unroll
        for (int mf = 0; mf < 4; mf++)
#pragma unroll
            for (int nf = 0; nf < 4; nf++) {
                const int row = m0 + wm + mf * 16 + (lane >> 2);   // token index
                const int col = (nbase) + wn + nf * 8 + (lane & 3) * 2;  // v feature 0..255
                const int kvh = col >> 6, d = col & 63;
                const int b = row >> 11, tok = row & 2047;
                float* base = g_vt + ((size_t)((b * HKV_ + kvh) * HD_ + d)) * T_ + tok;
                base[0]      = to_tf32(acc[mf][nf][0]);
                base[T_]     = to_tf32(acc[mf][nf][1]);
                base[8]      = to_tf32(acc[mf][nf][2]);
                base[T_ + 8] = to_tf32(acc[mf][nf][3]);
            }
    }
}

// ---------------------------------------------------------------------------
// RoPE in-place on g_qkv (q and k only).
// q gain = q_gain[h] * 1/sqrt(HD) * log2(e)  -> flash uses ex2 directly.
// ---------------------------------------------------------------------------
__global__ void rope_kernel(const float* __restrict__ q_gain)
{
    const int total_q = B_ * T_ * H_ * (HD_ / 2);
    const int total_k = B_ * T_ * HKV_ * (HD_ / 2);
    int idx = blockIdx.x * blockDim.x + threadIdx.x;
    if (idx >= total_q + total_k) return;

    const float LN = logf(10000.0f);
    const float LOG2E = 1.4426950408889634f;
    if (idx < total_q) {
        int j = idx & 31;
        int h = (idx >> 5) & 15;
        int t = (idx >> 9) & 2047;
        int b = idx >> 20;
        float invf = expf(-LN * ((float)(2 * j) / (float)HD_));
        float f = (float)t * invf;
        float c = cosf(f), s = sinf(f);
        float* base = g_qkv + ((size_t)(b * T_ + t)) * QKVD + h * HD_;
        float x1 = base[j], x2 = base[j + 32];
        float gain = q_gain[h] * 0.125f * LOG2E;
        base[j]      = to_tf32((x1 * c - x2 * s) * gain);
        base[j + 32] = to_tf32((x1 * s + x2 * c) * gain);
    } else {
        int i2 = idx - total_q;
        int j  = i2 & 31;
        int kv = (i2 >> 5) & 3;
        int t  = (i2 >> 7) & 2047;
        int b  = i2 >> 18;
        float invf = expf(-LN * ((float)(2 * j) / (float)HD_));
        float f = (float)t * invf;
        float c = cosf(f), s = sinf(f);
        float* base = g_qkv + ((size_t)(b * T_ + t)) * QKVD + KOFF + kv * HD_;
        float x1 = base[j], x2 = base[j + 32];
        base[j]      = to_tf32(x1 * c - x2 * s);
        base[j + 32] = to_tf32(x1 * s + x2 * c);
    }
}

// ---------------------------------------------------------------------------
// Tensor-core flash attention (causal, GQA), cp.async double-buffered K/V^T.
// No-max softmax with log2e pre-baked into q: p = ex2(s) directly (no fmin,
// no fmul, no tf32 round on p — mma truncates the A operand; the common-mode
// quantization cancels in O = sum(p v)/sum(p)).
// ---------------------------------------------------------------------------
#define FP2 68
#define TILEB (64 * FP2 * 4)
#define FLASH_SMEM ((2 * 64 + 2 * 64 + 128) * FP2 * 4)   // 104448 B

__global__ __launch_bounds__(256, 2) void flash_tc()
{
    extern __shared__ float sm[];
    float* Ks = sm;                      // [2][64 s][FP2] (cols = d)
    float* Vt = sm + 2 * 64 * FP2;       // [2][64 d][FP2] (cols = s)
    float* Ps = sm + 4 * 64 * FP2;       // [128 q][FP2]   (cols = s)

    const int qt   = (int)gridDim.x - 1 - (int)blockIdx.x;  // heavy blocks first
    const int h    = blockIdx.y;
    const int b    = blockIdx.z;
    const int tid  = threadIdx.x;
    const int lane = tid & 31;
    const int wid  = tid >> 5;
    const int wm   = wid * 16;
    const int kvh  = h >> 2;
    const int r0   = lane >> 2;
    const int c0   = lane & 3;

    const uint32_t Ks_u = smem_u32(Ks);
    const uint32_t Vt_u = smem_u32(Vt);
    const uint32_t Ps_u = smem_u32(Ps);

    const int kf_off = (lane & 7) * FP2 + (lane >> 3) * 4;   // K/V B-frag
    const int pa_off = ((lane & 7) + ((lane >> 3) & 1) * 8) * FP2 + ((lane >> 4) & 1) * 4;

    const int ld_r = tid >> 2;
    const int ld_c = (tid & 3) * 16;
    const float* kgbase = g_qkv + ((size_t)(b * T_ + ld_r)) * QKVD + KOFF + kvh * HD_ + ld_c;
    const float* vgbase = g_vt + ((size_t)((b * HKV_ + kvh) * HD_ + ld_r)) * T_ + ld_c;
    const uint32_t ks_dst = Ks_u + 4u * (ld_r * FP2 + ld_c);
    const uint32_t vt_dst = Vt_u + 4u * (ld_r * FP2 + ld_c);

#define ISSUE_TILE(S0, BUF)                                                   \
    {                                                                         \
        const float* kg = kgbase + (size_t)(S0) * QKVD;                       \
        const float* vg = vgbase + (S0);                                      \
        _Pragma("unroll") for (int u = 0; u < 4; u++) {                       \
            cp16(ks_dst + (BUF) * TILEB + 16 * u, kg + 4 * u);                \
            cp16(vt_dst + (BUF) * TILEB + 16 * u, vg + 4 * u);                \
        }                                                                     \
    }

    // Q fragments in registers (already tf32, pre-scaled by gain*log2e)
    uint32_t qf[8][4];
    {
        const float* q0 = g_qkv + ((size_t)(b * T_ + qt * 128 + wm + r0)) * QKVD + h * HD_;
        const float* q1 = q0 + (size_t)8 * QKVD;
#pragma unroll
        for (int kb = 0; kb < 8; kb++) {
            qf[kb][0] = __float_as_uint(q0[kb * 8 + c0]);
            qf[kb][1] = __float_as_uint(q1[kb * 8 + c0]);
            qf[kb][2] = __float_as_uint(q0[kb * 8 + c0 + 4]);
            qf[kb][3] = __float_as_uint(q1[kb * 8 + c0 + 4]);
        }
    }

    float oacc[8][4];
#pragma unroll
    for (int nf = 0; nf < 8; nf++)
#pragma unroll
        for (int r = 0; r < 4; r++) oacc[nf][r] = 0.f;
    float lp0 = 0.f, lp1 = 0.f;

    const int qi0 = qt * 128 + wm + r0;
    const int qi1 = qi0 + 8;
    const int ntiles = (qt + 1) * 2;

    ISSUE_TILE(0, 0); cp_commit();
    ISSUE_TILE(64, 1); cp_commit();

    for (int it = 0; it < ntiles; it++) {
        const int s0 = it * 64;
        cp_wait1();
        __syncthreads();
        const uint32_t ksb = Ks_u + (uint32_t)(it & 1) * TILEB;
        const uint32_t vtb = Vt_u + (uint32_t)(it & 1) * TILEB;

        if (s0 <= qt * 128 + wm + 15) {
            float sacc[8][4];
#pragma unroll
            for (int nf = 0; nf < 8; nf++)
#pragma unroll
                for (int r = 0; r < 4; r++) sacc[nf][r] = 0.f;

#pragma unroll
            for (int kbp = 0; kbp < 4; kbp++) {
#pragma unroll
                for (int nf = 0; nf < 8; nf++) {
                    uint32_t kb4[4];
                    ldm_x4(kb4, ksb + 4u * (nf * 8 * FP2 + kbp * 16 + kf_off));
                    mma_tf32(sacc[nf], qf[2 * kbp],     kb4);
                    mma_tf32(sacc[nf], qf[2 * kbp + 1], kb4 + 2);
                }
            }

            if (s0 + 63 > qt * 128 + wm) {   // causal mask near diagonal
#pragma unroll
                for (int nf = 0; nf < 8; nf++) {
                    int sj = s0 + nf * 8 + 2 * c0;
                    if (sj > qi0)     sacc[nf][0] = -1e30f;
                    if (sj + 1 > qi0) sacc[nf][1] = -1e30f;
                    if (sj > qi1)     sacc[nf][2] = -1e30f;
                    if (sj + 1 > qi1) sacc[nf][3] = -1e30f;
                }
            }

            // p = 2^s  (log2e pre-baked into q; masked -> 2^-1e30 = 0)
#pragma unroll
            for (int nf = 0; nf < 8; nf++) {
                float p0 = ex2f(sacc[nf][0]);
                float p1 = ex2f(sacc[nf][1]);
                float p2 = ex2f(sacc[nf][2]);
                float p3 = ex2f(sacc[nf][3]);
                lp0 += p0 + p1; lp1 += p2 + p3;
                *(float2*)&Ps[(wm + r0)     * FP2 + nf * 8 + 2 * c0] = make_float2(p0, p1);
                *(float2*)&Ps[(wm + r0 + 8) * FP2 + nf * 8 + 2 * c0] = make_float2(p2, p3);
            }

            __syncwarp();

            // O += P @ V  (V^T tile, same B-frag pattern as K)
#pragma unroll
            for (int kbp = 0; kbp < 4; kbp++) {
                uint32_t pa0[4], pa1[4];
                ldm_x4(pa0, Ps_u + 4u * (wm * FP2 + (2 * kbp)     * 8 + pa_off));
                ldm_x4(pa1, Ps_u + 4u * (wm * FP2 + (2 * kbp + 1) * 8 + pa_off));
#pragma unroll
                for (int nf = 0; nf < 8; nf++) {
                    uint32_t vb[4];
                    ldm_x4(vb, vtb + 4u * (nf * 8 * FP2 + kbp * 16 + kf_off));
                    mma_tf32(oacc[nf], pa0, vb);
                    mma_tf32(oacc[nf], pa1, vb + 2);
                }
            }
        }
        __syncthreads();
        if (it + 2 < ntiles) ISSUE_TILE(s0 + 128, it & 1);
        cp_commit();
    }

    lp0 += __shfl_xor_sync(0xffffffff, lp0, 1);
    lp0 += __shfl_xor_sync(0xffffffff, lp0, 2);
    lp1 += __shfl_xor_sync(0xffffffff, lp1, 1);
    lp1 += __shfl_xor_sync(0xffffffff, lp1, 2);
    float il0 = 1.0f / lp0, il1 = 1.0f / lp1;
    float* o0 = g_o + ((size_t)(b * T_ + qi0)) * D_ + h * HD_;
    float* o1 = g_o + ((size_t)(b * T_ + qi1)) * D_ + h * HD_;
#pragma unroll
    for (int nf = 0; nf < 8; nf++) {
        *(float2*)(o0 + nf * 8 + 2 * c0) = make_float2(to_tf32(oacc[nf][0] * il0), to_tf32(oacc[nf][1] * il0));
        *(float2*)(o1 + nf * 8 + 2 * c0) = make_float2(to_tf32(oacc[nf][2] * il1), to_tf32(oacc[nf][3] * il1));
    }
}

// ---------------------------------------------------------------------------
// Launch
// ---------------------------------------------------------------------------
extern "C" void kernel_launch(void* const* d_in, const int* in_sizes, int n_in,
                              void* d_out, int out_size)
{
    (void)in_sizes; (void)n_in; (void)out_size;
    const float* x      = (const float*)d_in[0];
    const float* Wq     = (const float*)d_in[1];
    const float* Wk     = (const float*)d_in[2];
    const float* Wv     = (const float*)d_in[3];
    const float* Wp     = (const float*)d_in[4];
    const float* q_gain = (const float*)d_in[5];
    float* out = (float*)d_out;

    float *qkvb, *ob, *pre;
    cudaGetSymbolAddress((void**)&qkvb, g_qkv);
    cudaGetSymbolAddress((void**)&ob, g_o);
    cudaGetSymbolAddress((void**)&pre, g_pre);

    cudaFuncSetAttribute(flash_tc, cudaFuncAttributeMaxDynamicSharedMemorySize, FLASH_SMEM);

    const int M = B_ * T_;   // 4096

    preround_kernel<<<(PRE_TOTAL / 4 + 255) / 256, 256>>>(x, Wq, Wk, Wv, Wp);

    gemm_qkv<<<dim3(QKVD / 128, M / 128), 256>>>(
        pre + PRE_X, pre + PRE_WQ, pre + PRE_WK, pre + PRE_WV, qkvb, M, D_);

    const int total = B_ * T_ * (H_ + HKV_) * (HD_ / 2);
    rope_kernel<<<(total + 255) / 256, 256>>>(q_gain);

    flash_tc<<<dim3(T_ / 128, H_, B_), 256, FLASH_SMEM>>>();

    gemm_tf32_nt<<<dim3(D_ / 128, M / 128), 256>>>(ob, pre + PRE_WP, out, M, D_, D_);
}

// round 13
// speedup vs baseline: 1.1691x; 1.0832x over previous
#include <cuda_runtime.h>
#include <math.h>
#include <stdint.h>

#define B_   2
#define T_   2048
#define D_   1024
#define H_   16
#define HKV_ 4
#define HD_  64
#define G_   4

#define QKVD 1536      // fused qkv row width: 1024 q | 256 k | 256 v
#define KOFF 1024
#define VOFF 1280

// Scratch (static device globals — no allocation in kernel_launch)
__device__ float g_qkv[(size_t)B_ * T_ * QKVD];
__device__ float g_vt[(size_t)B_ * HKV_ * HD_ * T_];   // V transposed: [b][kvh][d][t]
__device__ float g_o[(size_t)B_ * T_ * D_];
// pre-rounded (tf32) copies: x | Wq | Wk | Wv | Wp
#define PRE_X  0
#define PRE_WQ (4096 * 1024)
#define PRE_WK (PRE_WQ + 1024 * 1024)
#define PRE_WV (PRE_WK + 256 * 1024)
#define PRE_WP (PRE_WV + 256 * 1024)
#define PRE_TOTAL (PRE_WP + 1024 * 1024)
__device__ float g_pre[(size_t)PRE_TOTAL];

__device__ __forceinline__ float to_tf32(float x) {
    float r;
    asm("cvt.rna.tf32.f32 %0, %1;" : "=f"(r) : "f"(x));
    return r;
}

__device__ __forceinline__ float ex2f(float x) {
    float r;
    asm("ex2.approx.f32 %0, %1;" : "=f"(r) : "f"(x));
    return r;
}

__device__ __forceinline__ void mma_tf32(float* d, const uint32_t* a, const uint32_t* b) {
    asm volatile(
        "mma.sync.aligned.m16n8k8.row.col.f32.tf32.tf32.f32 "
        "{%0,%1,%2,%3}, {%4,%5,%6,%7}, {%8,%9}, {%0,%1,%2,%3};"
        : "+f"(d[0]), "+f"(d[1]), "+f"(d[2]), "+f"(d[3])
        : "r"(a[0]), "r"(a[1]), "r"(a[2]), "r"(a[3]), "r"(b[0]), "r"(b[1]));
}

__device__ __forceinline__ uint32_t smem_u32(const void* p) {
    return (uint32_t)__cvta_generic_to_shared(p);
}

__device__ __forceinline__ void ldm_x4(uint32_t* r, uint32_t a) {
    asm volatile("ldmatrix.sync.aligned.m8n8.x4.shared.b16 {%0,%1,%2,%3}, [%4];"
        : "=r"(r[0]), "=r"(r[1]), "=r"(r[2]), "=r"(r[3]) : "r"(a));
}

__device__ __forceinline__ void cp16(uint32_t dst, const void* src) {
    asm volatile("cp.async.cg.shared.global [%0], [%1], 16;" :: "r"(dst), "l"(src));
}
__device__ __forceinline__ void cp_commit() {
    asm volatile("cp.async.commit_group;");
}
__device__ __forceinline__ void cp_wait0() {
    asm volatile("cp.async.wait_group 0;");
}
__device__ __forceinline__ void cp_wait1() {
    asm volatile("cp.async.wait_group 1;");
}

// ---------------------------------------------------------------------------
// Pre-round inputs to tf32 (rna) into g_pre.
// ---------------------------------------------------------------------------
__global__ void preround_kernel(const float* __restrict__ x,
                                const float* __restrict__ Wq,
                                const float* __restrict__ Wk,
                                const float* __restrict__ Wv,
                                const float* __restrict__ Wp)
{
    int i4 = blockIdx.x * blockDim.x + threadIdx.x;
    int i = i4 * 4;
    if (i >= PRE_TOTAL) return;
    const float* src;
    int off;
    if (i < PRE_WQ)      { src = x;  off = i - PRE_X;  }
    else if (i < PRE_WK) { src = Wq; off = i - PRE_WQ; }
    else if (i < PRE_WV) { src = Wk; off = i - PRE_WK; }
    else if (i < PRE_WP) { src = Wv; off = i - PRE_WV; }
    else                 { src = Wp; off = i - PRE_WP; }
    float4 v = *(const float4*)(src + off);
    *(float4*)(g_pre + i) = make_float4(to_tf32(v.x), to_tf32(v.y), to_tf32(v.z), to_tf32(v.w));
}

// ---------------------------------------------------------------------------
// TF32 GEMM mainloop (128x128 tile, K-chunk 16, 8 warps 2m x 4n)
// 3-stage cp.async, single barrier per chunk, no inner-loop cvt.  (R8 config)
// ---------------------------------------------------------------------------
#define GP 20
#define SBYTES (128 * GP * 4)

#define GEMM_MAIN(BSEL, NBASE)                                                             \
    __shared__ float As[3][128][GP];                                                       \
    __shared__ float Bs[3][128][GP];                                                       \
    const int m0   = blockIdx.y * 128;                                                     \
    const int t    = threadIdx.x;                                                          \
    const int lane = t & 31;                                                               \
    const int wid  = t >> 5;                                                               \
    const int wm   = (wid >> 2) * 64;                                                      \
    const int wn   = (wid & 3) * 32;                                                       \
    const int lr = t >> 1;                                                                 \
    const int kg = (t & 1) * 8;                                                            \
    const uint32_t As_u = smem_u32(&As[0][0][0]);                                          \
    const uint32_t Bs_u = smem_u32(&Bs[0][0][0]);                                          \
    const uint32_t a_st = As_u + 4u * (lr * GP + kg);                                      \
    const uint32_t b_st = Bs_u + 4u * (lr * GP + kg);                                      \
    const int a_off = ((lane & 7) + ((lane >> 3) & 1) * 8) * GP + ((lane >> 4) & 1) * 4;   \
    const int b_off = ((lane & 7) + ((lane >> 4) & 1) * 8) * GP + ((lane >> 3) & 1) * 4;   \
    float acc[4][4][4];                                                                    \
    _Pragma("unroll") for (int i = 0; i < 4; i++)                                          \
    _Pragma("unroll") for (int j = 0; j < 4; j++)                                          \
    _Pragma("unroll") for (int r = 0; r < 4; r++) acc[i][j][r] = 0.f;                      \
    const float* Abase = A + (size_t)(m0 + lr) * K + kg;                                   \
    const float* Bbase = (BSEL) + (size_t)((NBASE) + lr) * K + kg;                         \
    const int nk = K / 16;                                                                 \
    _Pragma("unroll") for (int s = 0; s < 2; s++) {                                        \
        cp16(a_st + s * SBYTES,      Abase + s * 16);                                      \
        cp16(a_st + s * SBYTES + 16, Abase + s * 16 + 4);                                  \
        cp16(b_st + s * SBYTES,      Bbase + s * 16);                                      \
        cp16(b_st + s * SBYTES + 16, Bbase + s * 16 + 4);                                  \
        cp_commit();                                                                       \
    }                                                                                      \
    for (int it = 0; it < nk; it++) {                                                      \
        cp_wait1();                                                                        \
        __syncthreads();                                                                   \
        if (it + 2 < nk) {                                                                 \
            const int buf = (it + 2) % 3;                                                  \
            cp16(a_st + buf * SBYTES,      Abase + (it + 2) * 16);                         \
            cp16(a_st + buf * SBYTES + 16, Abase + (it + 2) * 16 + 4);                     \
            cp16(b_st + buf * SBYTES,      Bbase + (it + 2) * 16);                         \
            cp16(b_st + buf * SBYTES + 16, Bbase + (it + 2) * 16 + 4);                     \
        }                                                                                  \
        cp_commit();                                                                       \
        const int cur = it % 3;                                                            \
        const uint32_t abuf = As_u + (uint32_t)cur * SBYTES;                               \
        const uint32_t bbuf = Bs_u + (uint32_t)cur * SBYTES;                               \
        uint32_t af[2][4][4], bf[2][2][4];                                                 \
        _Pragma("unroll") for (int ks2 = 0; ks2 < 2; ks2++) {                              \
            _Pragma("unroll") for (int mf = 0; mf < 4; mf++)                               \
                ldm_x4(af[ks2][mf], abuf + 4u * ((wm + mf * 16) * GP + ks2 * 8 + a_off));  \
            _Pragma("unroll") for (int np = 0; np < 2; np++)                               \
                ldm_x4(bf[ks2][np], bbuf + 4u * ((wn + np * 16) * GP + ks2 * 8 + b_off));  \
        }                                                                                  \
        _Pragma("unroll") for (int ks2 = 0; ks2 < 2; ks2++)                                \
        _Pragma("unroll") for (int mf = 0; mf < 4; mf++)                                   \
        _Pragma("unroll") for (int np = 0; np < 2; np++) {                                 \
            mma_tf32(acc[mf][np * 2],     af[ks2][mf], bf[ks2][np]);                       \
            mma_tf32(acc[mf][np * 2 + 1], af[ks2][mf], bf[ks2][np] + 2);                   \
        }                                                                                  \
    }

__global__ __launch_bounds__(256, 2) void gemm_tf32_nt(
    const float* __restrict__ A, const float* __restrict__ B,
    float* __restrict__ C, int M, int N, int K)
{
    GEMM_MAIN(B, blockIdx.x * 128)
    const int n0 = blockIdx.x * 128;
#pragma unroll
    for (int mf = 0; mf < 4; mf++)
#pragma unroll
        for (int nf = 0; nf < 4; nf++) {
            const int row = m0 + wm + mf * 16 + (lane >> 2);
            const int col = n0 + wn + nf * 8 + (lane & 3) * 2;
            *(float2*)(C + (size_t)row * N + col)       = make_float2(acc[mf][nf][0], acc[mf][nf][1]);
            *(float2*)(C + (size_t)(row + 8) * N + col) = make_float2(acc[mf][nf][2], acc[mf][nf][3]);
        }
}

// QKV GEMM: q/k blocks -> g_qkv rows (tf32-rounded); v blocks -> g_vt TRANSPOSED.
__global__ __launch_bounds__(256, 2) void gemm_qkv(
    const float* __restrict__ A, const float* __restrict__ Wq,
    const float* __restrict__ Wk, const float* __restrict__ Wv,
    float* __restrict__ C, int M, int K)
{
    const int nblk = blockIdx.x * 128;
    const float* Bsel; int nbase;
    if (nblk < KOFF)      { Bsel = Wq; nbase = nblk; }
    else if (nblk < VOFF) { Bsel = Wk; nbase = nblk - KOFF; }
    else                  { Bsel = Wv; nbase = nblk - VOFF; }
    GEMM_MAIN(Bsel, nbase)
    if (nblk < VOFF) {
#pragma unroll
        for (int mf = 0; mf < 4; mf++)
#pragma unroll
            for (int nf = 0; nf < 4; nf++) {
                const int row = m0 + wm + mf * 16 + (lane >> 2);
                const int col = nblk + wn + nf * 8 + (lane & 3) * 2;
                *(float2*)(C + (size_t)row * QKVD + col) =
                    make_float2(to_tf32(acc[mf][nf][0]), to_tf32(acc[mf][nf][1]));
                *(float2*)(C + (size_t)(row + 8) * QKVD + col) =
                    make_float2(to_tf32(acc[mf][nf][2]), to_tf32(acc[mf][nf][3]));
            }
    } else {
        // V: write transposed g_vt[b][kvh][d][t]
#pragma unroll
        for (int mf = 0; mf < 4; mf++)
#pragma unroll
            for (int nf = 0; nf < 4; nf++) {
                const int row = m0 + wm + mf * 16 + (lane >> 2);   // token index
                const int col = (nbase) + wn + nf * 8 + (lane & 3) * 2;  // v feature 0..255
                const int kvh = col >> 6, d = col & 63;
                const int b = row >> 11, tok = row & 2047;
                float* base = g_vt + ((size_t)((b * HKV_ + kvh) * HD_ + d)) * T_ + tok;
                base[0]      = to_tf32(acc[mf][nf][0]);
                base[T_]     = to_tf32(acc[mf][nf][1]);
                base[8]      = to_tf32(acc[mf][nf][2]);
                base[T_ + 8] = to_tf32(acc[mf][nf][3]);
            }
    }
}

// ---------------------------------------------------------------------------
// RoPE in-place on g_qkv (q and k only).
// q gain = q_gain[h] * 1/sqrt(HD) * log2(e)  -> flash uses ex2 directly.
// ---------------------------------------------------------------------------
__global__ void rope_kernel(const float* __restrict__ q_gain)
{
    const int total_q = B_ * T_ * H_ * (HD_ / 2);
    const int total_k = B_ * T_ * HKV_ * (HD_ / 2);
    int idx = blockIdx.x * blockDim.x + threadIdx.x;
    if (idx >= total_q + total_k) return;

    const float LN = logf(10000.0f);
    const float LOG2E = 1.4426950408889634f;
    if (idx < total_q) {
        int j = idx & 31;
        int h = (idx >> 5) & 15;
        int t = (idx >> 9) & 2047;
        int b = idx >> 20;
        float invf = expf(-LN * ((float)(2 * j) / (float)HD_));
        float f = (float)t * invf;
        float c = cosf(f), s = sinf(f);
        float* base = g_qkv + ((size_t)(b * T_ + t)) * QKVD + h * HD_;
        float x1 = base[j], x2 = base[j + 32];
        float gain = q_gain[h] * 0.125f * LOG2E;
        base[j]      = to_tf32((x1 * c - x2 * s) * gain);
        base[j + 32] = to_tf32((x1 * s + x2 * c) * gain);
    } else {
        int i2 = idx - total_q;
        int j  = i2 & 31;
        int kv = (i2 >> 5) & 3;
        int t  = (i2 >> 7) & 2047;
        int b  = i2 >> 18;
        float invf = expf(-LN * ((float)(2 * j) / (float)HD_));
        float f = (float)t * invf;
        float c = cosf(f), s = sinf(f);
        float* base = g_qkv + ((size_t)(b * T_ + t)) * QKVD + KOFF + kv * HD_;
        float x1 = base[j], x2 = base[j + 32];
        base[j]      = to_tf32(x1 * c - x2 * s);
        base[j + 32] = to_tf32(x1 * s + x2 * c);
    }
}

// ---------------------------------------------------------------------------
// Tensor-core flash attention (causal, GQA).
// SINGLE barrier per KV tile: 2-buffer cp.async at prefetch distance 1
// (buffer (it+1)&1 was last read at tile it-1 -> safe to overwrite after
// this tile's barrier). K/V tiles 64x64 floats, XOR-swizzled (16B unit ^=
// row&7), no padding -> 16 KB/tile. Ps: 64 cols at pitch 68 (R11-proven
// conflict-free A-frag layout).
// No-max softmax: p = ex2(s) (log2e baked into q); normalize at the end.
// ---------------------------------------------------------------------------
#define TILEB 16384
#define PSP 68
#define FLASH_SMEM (4 * TILEB + 128 * PSP * 4)   // 100352 B

__global__ __launch_bounds__(256, 2) void flash_tc()
{
    extern __shared__ float sm[];
    float* Ks = sm;                      // [2][64 s][64 d] swizzled
    float* Vt = sm + 2 * 64 * 64;        // [2][64 d][64 t] swizzled
    float* Ps = sm + 4 * 64 * 64;        // [128 q][PSP]

    const int qt   = (int)gridDim.x - 1 - (int)blockIdx.x;  // heavy blocks first
    const int h    = blockIdx.y;
    const int b    = blockIdx.z;
    const int tid  = threadIdx.x;
    const int lane = tid & 31;
    const int wid  = tid >> 5;
    const int wm   = wid * 16;
    const int kvh  = h >> 2;
    const int r0   = lane >> 2;
    const int c0   = lane & 3;

    const uint32_t Ks_u = smem_u32(Ks);
    const uint32_t Vt_u = smem_u32(Vt);
    const uint32_t Ps_u = smem_u32(Ps);

    // ldmatrix lane geometry
    const int lr8 = lane & 7;        // row within 8-row group
    const int lh  = lane >> 3;       // matrix index 0..3
    // K/V B-frag swizzled 16B-unit offsets per kbp (bytes)
    uint32_t kvsw[4];
#pragma unroll
    for (int kbp = 0; kbp < 4; kbp++)
        kvsw[kbp] = (uint32_t)(((kbp * 4 + lh) ^ lr8) << 4);
    const uint32_t kv_row = (uint32_t)(lr8 << 8);   // + (nf*8)<<8 at use site
    // P A-frag offset (floats), pitch 68 (R11 layout)
    const int pa_off = ((lane & 7) + ((lane >> 3) & 1) * 8) * PSP + ((lane >> 4) & 1) * 4;

    // cp.async loaders: thread -> row s = tid>>2, unit group g = tid&3
    const int ld_s = tid >> 2;
    const int ld_g = tid & 3;
    uint32_t swst[4];
#pragma unroll
    for (int j = 0; j < 4; j++)
        swst[j] = (uint32_t)((ld_s << 8) + (((4 * ld_g + j) ^ (ld_s & 7)) << 4));
    const float* kgbase = g_qkv + ((size_t)(b * T_ + ld_s)) * QKVD + KOFF + kvh * HD_ + ld_g * 16;
    const float* vgbase = g_vt + ((size_t)((b * HKV_ + kvh) * HD_ + ld_s)) * T_ + ld_g * 16;

#define ISSUE_TILE(S0, BUF)                                                   \
    {                                                                         \
        const float* kg = kgbase + (size_t)(S0) * QKVD;                       \
        const float* vg = vgbase + (S0);                                      \
        const uint32_t kb_ = Ks_u + (BUF) * TILEB;                            \
        const uint32_t vb_ = Vt_u + (BUF) * TILEB;                            \
        _Pragma("unroll") for (int u = 0; u < 4; u++) {                       \
            cp16(kb_ + swst[u], kg + 4 * u);                                  \
            cp16(vb_ + swst[u], vg + 4 * u);                                  \
        }                                                                     \
    }

    // Q fragments in registers (already tf32, pre-scaled by gain*log2e)
    uint32_t qf[8][4];
    {
        const float* q0 = g_qkv + ((size_t)(b * T_ + qt * 128 + wm + r0)) * QKVD + h * HD_;
        const float* q1 = q0 + (size_t)8 * QKVD;
#pragma unroll
        for (int kb = 0; kb < 8; kb++) {
            qf[kb][0] = __float_as_uint(q0[kb * 8 + c0]);
            qf[kb][1] = __float_as_uint(q1[kb * 8 + c0]);
            qf[kb][2] = __float_as_uint(q0[kb * 8 + c0 + 4]);
            qf[kb][3] = __float_as_uint(q1[kb * 8 + c0 + 4]);
        }
    }

    float oacc[8][4];
#pragma unroll
    for (int nf = 0; nf < 8; nf++)
#pragma unroll
        for (int r = 0; r < 4; r++) oacc[nf][r] = 0.f;
    float lp0 = 0.f, lp1 = 0.f;

    const int qi0 = qt * 128 + wm + r0;
    const int qi1 = qi0 + 8;
    const int ntiles = (qt + 1) * 2;

    // prologue: tile 0 only (prefetch distance 1)
    ISSUE_TILE(0, 0); cp_commit();

    for (int it = 0; it < ntiles; it++) {
        const int s0 = it * 64;
        cp_wait0();
        __syncthreads();                       // the ONLY barrier per tile
        if (it + 1 < ntiles) ISSUE_TILE(s0 + 64, (it + 1) & 1);
        cp_commit();

        const uint32_t ksb = Ks_u + (uint32_t)(it & 1) * TILEB;
        const uint32_t vtb = Vt_u + (uint32_t)(it & 1) * TILEB;

        if (s0 <= qt * 128 + wm + 15) {
            // S = Q @ K^T (per-warp 16x64)
            float sacc[8][4];
#pragma unroll
            for (int nf = 0; nf < 8; nf++)
#pragma unroll
                for (int r = 0; r < 4; r++) sacc[nf][r] = 0.f;

#pragma unroll
            for (int kbp = 0; kbp < 4; kbp++) {
#pragma unroll
                for (int nf = 0; nf < 8; nf++) {
                    uint32_t kb4[4];
                    ldm_x4(kb4, ksb + ((uint32_t)(nf * 8) << 8) + kv_row + kvsw[kbp]);
                    mma_tf32(sacc[nf], qf[2 * kbp],     kb4);
                    mma_tf32(sacc[nf], qf[2 * kbp + 1], kb4 + 2);
                }
            }

            if (s0 + 63 > qt * 128 + wm) {   // causal mask near diagonal
#pragma unroll
                for (int nf = 0; nf < 8; nf++) {
                    int sj = s0 + nf * 8 + 2 * c0;
                    if (sj > qi0)     sacc[nf][0] = -1e30f;
                    if (sj + 1 > qi0) sacc[nf][1] = -1e30f;
                    if (sj > qi1)     sacc[nf][2] = -1e30f;
                    if (sj + 1 > qi1) sacc[nf][3] = -1e30f;
                }
            }

            // p = 2^s  (masked -> 2^-1e30 = 0)
#pragma unroll
            for (int nf = 0; nf < 8; nf++) {
                float p0 = ex2f(sacc[nf][0]);
                float p1 = ex2f(sacc[nf][1]);
                float p2 = ex2f(sacc[nf][2]);
                float p3 = ex2f(sacc[nf][3]);
                lp0 += p0 + p1; lp1 += p2 + p3;
                *(float2*)&Ps[(wm + r0)     * PSP + nf * 8 + 2 * c0] = make_float2(p0, p1);
                *(float2*)&Ps[(wm + r0 + 8) * PSP + nf * 8 + 2 * c0] = make_float2(p2, p3);
            }

            __syncwarp();

            // O += P @ V  (V^T tile, same swizzled B-frag pattern as K)
#pragma unroll
            for (int kbp = 0; kbp < 4; kbp++) {
                uint32_t pa0[4], pa1[4];
                ldm_x4(pa0, Ps_u + 4u * (wm * PSP + (2 * kbp)     * 8 + pa_off));
                ldm_x4(pa1, Ps_u + 4u * (wm * PSP + (2 * kbp + 1) * 8 + pa_off));
#pragma unroll
                for (int nf = 0; nf < 8; nf++) {
                    uint32_t vb[4];
                    ldm_x4(vb, vtb + ((uint32_t)(nf * 8) << 8) + kv_row + kvsw[kbp]);
                    mma_tf32(oacc[nf], pa0, vb);
                    mma_tf32(oacc[nf], pa1, vb + 2);
                }
            }
        }
    }

    // one-time row-sum reduction + normalize + write O
    lp0 += __shfl_xor_sync(0xffffffff, lp0, 1);
    lp0 += __shfl_xor_sync(0xffffffff, lp0, 2);
    lp1 += __shfl_xor_sync(0xffffffff, lp1, 1);
    lp1 += __shfl_xor_sync(0xffffffff, lp1, 2);
    float il0 = 1.0f / lp0, il1 = 1.0f / lp1;
    float* o0 = g_o + ((size_t)(b * T_ + qi0)) * D_ + h * HD_;
    float* o1 = g_o + ((size_t)(b * T_ + qi1)) * D_ + h * HD_;
#pragma unroll
    for (int nf = 0; nf < 8; nf++) {
        *(float2*)(o0 + nf * 8 + 2 * c0) = make_float2(to_tf32(oacc[nf][0] * il0), to_tf32(oacc[nf][1] * il0));
        *(float2*)(o1 + nf * 8 + 2 * c0) = make_float2(to_tf32(oacc[nf][2] * il1), to_tf32(oacc[nf][3] * il1));
    }
}

// ---------------------------------------------------------------------------
// Launch
// ---------------------------------------------------------------------------
extern "C" void kernel_launch(void* const* d_in, const int* in_sizes, int n_in,
                              void* d_out, int out_size)
{
    (void)in_sizes; (void)n_in; (void)out_size;
    const float* x      = (const float*)d_in[0];
    const float* Wq     = (const float*)d_in[1];
    const float* Wk     = (const float*)d_in[2];
    const float* Wv     = (const float*)d_in[3];
    const float* Wp     = (const float*)d_in[4];
    const float* q_gain = (const float*)d_in[5];
    float* out = (float*)d_out;

    float *qkvb, *ob, *pre;
    cudaGetSymbolAddress((void**)&qkvb, g_qkv);
    cudaGetSymbolAddress((void**)&ob, g_o);
    cudaGetSymbolAddress((void**)&pre, g_pre);

    cudaFuncSetAttribute(flash_tc, cudaFuncAttributeMaxDynamicSharedMemorySize, FLASH_SMEM);

    const int M = B_ * T_;   // 4096

    preround_kernel<<<(PRE_TOTAL / 4 + 255) / 256, 256>>>(x, Wq, Wk, Wv, Wp);

    gemm_qkv<<<dim3(QKVD / 128, M / 128), 256>>>(
        pre + PRE_X, pre + PRE_WQ, pre + PRE_WK, pre + PRE_WV, qkvb, M, D_);

    const int total = B_ * T_ * (H_ + HKV_) * (HD_ / 2);
    rope_kernel<<<(total + 255) / 256, 256>>>(q_gain);

    flash_tc<<<dim3(T_ / 128, H_, B_), 256, FLASH_SMEM>>>();

    gemm_tf32_nt<<<dim3(D_ / 128, M / 128), 256>>>(ob, pre + PRE_WP, out, M, D_, D_);
}